// round 14
// baseline (speedup 1.0000x reference)
#include <cuda_runtime.h>
#include <math.h>

// ---------------- global scratch (allocation-free rule) ----------------
static __device__ float2 g_p1[4096 * 845];   // L1 pooled output as {silu, t}
static __device__ float2 g_p2[4096 * 405];   // L2 output as {silu, t}
static __device__ float  g_h[4096 * 98];     // L3 conv output (flattened)
static __device__ float  g_fwT[98 * 200];    // fc_w transposed: [k][o]
// layer-2 packed coef tables: entry i=f*11+j
static __device__ ulonglong2 g_t01[125 * 11 * 2];  // [2i]={c0(o0,o1),c1}, [2i+1]={c2,c3}
static __device__ ulonglong2 g_t23[125 * 11 * 2];  // same for (o2,o3)
static __device__ float4     g_t4[125 * 11];       // scalar table for o4

typedef unsigned long long ull;

__device__ __forceinline__ ull pk2(float lo, float hi) {
    ull r; asm("mov.b64 %0,{%1,%2};" : "=l"(r) : "f"(lo), "f"(hi)); return r;
}
__device__ __forceinline__ void upk2(ull v, float& lo, float& hi) {
    asm("mov.b64 {%0,%1},%2;" : "=f"(lo), "=f"(hi) : "l"(v));
}
__device__ __forceinline__ ull fma2(ull a, ull b, ull c) {
    ull d; asm("fma.rn.f32x2 %0,%1,%2,%3;" : "=l"(d) : "l"(a), "l"(b), "l"(c)); return d;
}
__device__ __forceinline__ ull add2(ull a, ull b) {
    ull d; asm("add.rn.f32x2 %0,%1,%2;" : "=l"(d) : "l"(a), "l"(b)); return d;
}
// packed cubic for an output pair: qa={c0,c1}, qb={c2,c3}; returns acc + cubic
__device__ __forceinline__ ull cubic2(ull acc, ulonglong2 qa, ulonglong2 qb, ull u2) {
    ull t = fma2(qb.y, u2, qb.x);
    t = fma2(t, u2, qa.y);
    t = fma2(t, u2, qa.x);
    return add2(acc, t);
}

__device__ __forceinline__ float silu_f(float x) {
    return __fdividef(x, 1.0f + __expf(-x));
}
__device__ __forceinline__ float tmap(float x) { return (x + 1.0f) * 2.5f + 3.0f; }
__device__ __forceinline__ float cubic4(float4 q, float u) {
    return ((q.w * u + q.z) * u + q.y) * u + q.x;
}

__device__ __forceinline__ float4 coef_from_w(const float* __restrict__ ws, int row, int j) {
    float w[4];
#pragma unroll
    for (int k = 0; k < 4; k++) {
        int g = j - 3 + k;
        w[k] = (g >= 0 && g <= 7) ? __ldg(&ws[row * 8 + g]) : 0.0f;
    }
    const float s6 = 1.0f / 6.0f;
    float4 c;
    c.x = (w[0] + 4.0f * w[1] + w[2]) * s6;
    c.y = (w[2] - w[0]) * 0.5f;
    c.z = (w[0] - 2.0f * w[1] + w[2]) * 0.5f;
    c.w = (-w[0] + 3.0f * w[1] - 3.0f * w[2] + w[3]) * s6;
    return c;
}

// ---------------- setup: packed layer-2 tables + fc_w transpose ----------------
__global__ void build_tables(const float* __restrict__ ws2, const float* __restrict__ fcw) {
    int stride = gridDim.x * blockDim.x;
    int tid = blockIdx.x * blockDim.x + threadIdx.x;
    for (int i = tid; i < 125 * 11; i += stride) {
        int f = i / 11, j = i % 11;
        float4 q0 = coef_from_w(ws2, f, j);
        float4 q1 = coef_from_w(ws2, 125 + f, j);
        float4 q2 = coef_from_w(ws2, 250 + f, j);
        float4 q3 = coef_from_w(ws2, 375 + f, j);
        float4 q4 = coef_from_w(ws2, 500 + f, j);
        g_t01[2 * i]     = make_ulonglong2(pk2(q0.x, q1.x), pk2(q0.y, q1.y));
        g_t01[2 * i + 1] = make_ulonglong2(pk2(q0.z, q1.z), pk2(q0.w, q1.w));
        g_t23[2 * i]     = make_ulonglong2(pk2(q2.x, q3.x), pk2(q2.y, q3.y));
        g_t23[2 * i + 1] = make_ulonglong2(pk2(q2.z, q3.z), pk2(q2.w, q3.w));
        g_t4[i] = q4;
    }
    for (int i = tid; i < 200 * 98; i += stride) {
        int o = i / 98, k = i % 98;
        g_fwT[k * 200 + o] = fcw[i];
    }
}

// ---------------- Kernel 1: conv3(Cin=1,O=5) + maxpool2, 6 imgs, 512 thr ----------------
#define K1_IMGS 6
__global__ void __launch_bounds__(512)
k1_conv_pool(const float* __restrict__ x, const float* __restrict__ wb1,
             const float* __restrict__ ws1, int B) {
    __shared__ __align__(16) ulonglong2 t01s[9 * 11 * 2];
    __shared__ __align__(16) ulonglong2 t23s[9 * 11 * 2];
    __shared__ __align__(16) float4 t4s[9 * 11];
    __shared__ __align__(16) ulonglong2 wbp[9];   // {pk(w0,w1), pk(w2,w3)}
    __shared__ float wb4s[9];
    __shared__ float2 px[K1_IMGS * 784];
    int tid = threadIdx.x;
    int b0 = blockIdx.x * K1_IMGS;
    int nimg = min(K1_IMGS, B - b0);

    if (tid < 99) {
        int f = tid / 11, j = tid % 11;
        float4 q0 = coef_from_w(ws1, f, j);
        float4 q1 = coef_from_w(ws1, 9 + f, j);
        float4 q2 = coef_from_w(ws1, 18 + f, j);
        float4 q3 = coef_from_w(ws1, 27 + f, j);
        t4s[tid] = coef_from_w(ws1, 36 + f, j);
        t01s[2 * tid]     = make_ulonglong2(pk2(q0.x, q1.x), pk2(q0.y, q1.y));
        t01s[2 * tid + 1] = make_ulonglong2(pk2(q0.z, q1.z), pk2(q0.w, q1.w));
        t23s[2 * tid]     = make_ulonglong2(pk2(q2.x, q3.x), pk2(q2.y, q3.y));
        t23s[2 * tid + 1] = make_ulonglong2(pk2(q2.z, q3.z), pk2(q2.w, q3.w));
    }
    if (tid < 9) {
        wbp[tid] = make_ulonglong2(pk2(__ldg(&wb1[tid]), __ldg(&wb1[9 + tid])),
                                   pk2(__ldg(&wb1[18 + tid]), __ldg(&wb1[27 + tid])));
        wb4s[tid] = __ldg(&wb1[36 + tid]);
    }
    for (int i = tid; i < nimg * 784; i += 512) {
        float v = x[b0 * 784 + i];
        px[i] = make_float2(silu_f(v), tmap(v));
    }
    __syncthreads();

    for (int task = tid; task < nimg * 169; task += 512) {
        int li = task / 169, p = task % 169;
        int ph = p / 13, pw = p % 13;

        float s[16], u[16];
        int jj[16];
#pragma unroll
        for (int i = 0; i < 16; i++) {
            int r = i >> 2, c = i & 3;
            float2 st = px[li * 784 + (2 * ph + r) * 28 + 2 * pw + c];
            s[i] = st.x;
            float fj = floorf(st.y);
            jj[i] = (int)fj;
            u[i] = st.y - fj;
        }

        float best[5];
#pragma unroll
        for (int o = 0; o < 5; o++) best[o] = -3.0e38f;

#pragma unroll
        for (int d = 0; d < 4; d++) {
            int dy = d >> 1, dx = d & 1;
            ull acc01 = 0ULL, acc23 = 0ULL;
            float a4 = 0.0f;
#pragma unroll
            for (int r = 0; r < 3; r++)
#pragma unroll
            for (int c = 0; c < 3; c++) {
                int f = r * 3 + c;
                int i = (dy + r) * 4 + (dx + c);
                float sv = s[i];
                ull s2 = pk2(sv, sv);
                ulonglong2 wv = wbp[f];
                acc01 = fma2(s2, wv.x, acc01);
                acc23 = fma2(s2, wv.y, acc23);
                a4 += sv * wb4s[f];
                int j = jj[i];
                float uu = u[i];
                if ((unsigned)j <= 10u) {
                    int i2 = (f * 11 + j) * 2;
                    ull u2 = pk2(uu, uu);
                    acc01 = cubic2(acc01, t01s[i2], t01s[i2 + 1], u2);
                    acc23 = cubic2(acc23, t23s[i2], t23s[i2 + 1], u2);
                    a4 += cubic4(t4s[f * 11 + j], uu);
                }
            }
            float a0, a1, a2, a3;
            upk2(acc01, a0, a1);
            upk2(acc23, a2, a3);
            best[0] = fmaxf(best[0], a0); best[1] = fmaxf(best[1], a1);
            best[2] = fmaxf(best[2], a2); best[3] = fmaxf(best[3], a3);
            best[4] = fmaxf(best[4], a4);
        }
#pragma unroll
        for (int o = 0; o < 5; o++) {
            float v = best[o];
            g_p1[(b0 + li) * 845 + o * 169 + p] = make_float2(silu_f(v), tmap(v));
        }
    }
}

// ---------------- Kernel 2: conv5(Cin=5,O=5), packed f32x2, 9 imgs, 768 thr ----------------
// smem (bytes): wbp ull2[125] [0,2000); wb4 [2000,2500) pad 2512;
// t01 [2512,46512); t23 [46512,90512); t4 [90512,112512); in [112512,173352)
#define K2_IMGS 9
#define K2_SMEM (2512 + 44000 + 44000 + 22000 + K2_IMGS * 845 * 8)
__global__ void __launch_bounds__(768)
k2_conv(const float* __restrict__ wb2, int B) {
    extern __shared__ __align__(16) char smraw[];
    ulonglong2* wbp = reinterpret_cast<ulonglong2*>(smraw);            // 125
    float* wb4s = reinterpret_cast<float*>(smraw + 2000);              // 125
    ulonglong2* t01s = reinterpret_cast<ulonglong2*>(smraw + 2512);    // 2750
    ulonglong2* t23s = reinterpret_cast<ulonglong2*>(smraw + 46512);   // 2750
    float4* t4s = reinterpret_cast<float4*>(smraw + 90512);            // 1375
    float2* in = reinterpret_cast<float2*>(smraw + 112512);            // 9*845
    int tid = threadIdx.x;
    int b0 = blockIdx.x * K2_IMGS;
    int nimg = min(K2_IMGS, B - b0);

    for (int i = tid; i < 2750; i += 768) { t01s[i] = g_t01[i]; t23s[i] = g_t23[i]; }
    for (int i = tid; i < 1375; i += 768) t4s[i] = g_t4[i];
    for (int i = tid; i < 125; i += 768) {
        wbp[i] = make_ulonglong2(pk2(__ldg(&wb2[i]), __ldg(&wb2[125 + i])),
                                 pk2(__ldg(&wb2[250 + i]), __ldg(&wb2[375 + i])));
        wb4s[i] = __ldg(&wb2[500 + i]);
    }
    for (int i = tid; i < nimg * 845; i += 768) in[i] = g_p1[b0 * 845 + i];
    __syncthreads();

    int li = tid / 81, pos = tid % 81;
    if (li >= nimg) return;
    int oy = pos / 9, ox = pos % 9;

    ull acc01 = 0ULL, acc23 = 0ULL;
    float a4 = 0.0f;
    for (int c = 0; c < 5; c++) {
        const float2* inc = &in[li * 845 + c * 169];
        for (int kh = 0; kh < 5; kh++) {
            const float2* row = &inc[(oy + kh) * 13 + ox];
            int fbase = (c * 5 + kh) * 5;
#pragma unroll
            for (int kw = 0; kw < 5; kw++) {
                int f = fbase + kw;
                float2 st = row[kw];
                ull s2 = pk2(st.x, st.x);
                ulonglong2 wv = wbp[f];
                acc01 = fma2(s2, wv.x, acc01);
                acc23 = fma2(s2, wv.y, acc23);
                a4 += st.x * wb4s[f];
                float fj = floorf(st.y);
                int j = (int)fj;
                float u = st.y - fj;
                if ((unsigned)j <= 10u) {
                    int i2 = (f * 11 + j) * 2;
                    ull u2 = pk2(u, u);
                    acc01 = cubic2(acc01, t01s[i2], t01s[i2 + 1], u2);
                    acc23 = cubic2(acc23, t23s[i2], t23s[i2 + 1], u2);
                    a4 += cubic4(t4s[f * 11 + j], u);
                }
            }
        }
    }
    float a0, a1, a2, a3;
    upk2(acc01, a0, a1);
    upk2(acc23, a2, a3);
    int b = b0 + li;
    float acc[5] = {a0, a1, a2, a3, a4};
#pragma unroll
    for (int o = 0; o < 5; o++) {
        float v = acc[o];
        g_p2[b * 405 + o * 81 + pos] = make_float2(silu_f(v), tmap(v));
    }
}

// ---------------- Kernel 3: conv3(Cin=5,O=2), 10 imgs, 512 thr -> g_h ----------------
#define K3_IMGS 10
#define K3_SMEM (15840 + K3_IMGS * 405 * 8 + 45 * 8)
__global__ void __launch_bounds__(512)
k3_conv(const float* __restrict__ wb3, const float* __restrict__ ws3, int B) {
    extern __shared__ __align__(16) char smraw3[];
    float4* c3s = reinterpret_cast<float4*>(smraw3);             // 990
    float2* in  = reinterpret_cast<float2*>(smraw3 + 15840);     // 10*405
    float2* wbp = reinterpret_cast<float2*>(smraw3 + 15840 + K3_IMGS * 405 * 8); // 45
    int tid = threadIdx.x;
    int b0 = blockIdx.x * K3_IMGS;
    int nimg = min(K3_IMGS, B - b0);

    for (int i = tid; i < 990; i += 512) c3s[i] = coef_from_w(ws3, i / 11, i % 11);
    if (tid < 45) wbp[tid] = make_float2(__ldg(&wb3[tid]), __ldg(&wb3[45 + tid]));
    for (int i = tid; i < nimg * 405; i += 512) in[i] = g_p2[b0 * 405 + i];
    __syncthreads();

    for (int task = tid; task < nimg * 49; task += 512) {
        int li = task / 49, pos = task % 49;
        int oy = pos / 7, ox = pos % 7;
        float a0 = 0, a1 = 0;
        for (int c = 0; c < 5; c++) {
#pragma unroll
            for (int kh = 0; kh < 3; kh++)
#pragma unroll
            for (int kw = 0; kw < 3; kw++) {
                int f = (c * 3 + kh) * 3 + kw;
                float2 st = in[li * 405 + c * 81 + (oy + kh) * 9 + ox + kw];
                float2 wv = wbp[f];
                a0 += st.x * wv.x;
                a1 += st.x * wv.y;
                float fj = floorf(st.y);
                int j = (int)fj;
                float u = st.y - fj;
                if ((unsigned)j <= 10u) {
                    int i0 = f * 11 + j;
                    a0 += cubic4(c3s[i0], u);
                    a1 += cubic4(c3s[i0 + 495], u);
                }
            }
        }
        int b = b0 + li;
        g_h[b * 98 + pos]      = a0;   // flatten order o*49 + pos
        g_h[b * 98 + 49 + pos] = a1;
    }
}

// ---------------- Kernel 4: FC, warp-per-image, fwT via LDG (L1-resident) ----------------
#define K4_WARPS 16
__global__ void __launch_bounds__(512)
k4_fc(const float* __restrict__ fcb, float* __restrict__ out, int B) {
    __shared__ float hs[K4_WARPS][100];
    int tid = threadIdx.x;
    int wid = tid / 32, lane = tid % 32;
    int img = blockIdx.x * K4_WARPS + wid;
    if (img >= B) return;

    for (int k = lane; k < 98; k += 32) hs[wid][k] = g_h[img * 98 + k];
    __syncwarp();

    const float4* fwT4 = reinterpret_cast<const float4*>(g_fwT);
    const float4* fb4  = reinterpret_cast<const float4*>(fcb);
    const float*  hr   = hs[wid];
    float4* o4 = reinterpret_cast<float4*>(out + img * 200);

    {
        float4 acc = __ldg(&fb4[lane]);
#pragma unroll 7
        for (int k = 0; k < 98; k++) {
            float hv = hr[k];
            float4 w = __ldg(&fwT4[k * 50 + lane]);
            acc.x += hv * w.x; acc.y += hv * w.y; acc.z += hv * w.z; acc.w += hv * w.w;
        }
        o4[lane] = acc;
    }
    if (lane < 18) {
        float4 acc = __ldg(&fb4[32 + lane]);
#pragma unroll 7
        for (int k = 0; k < 98; k++) {
            float hv = hr[k];
            float4 w = __ldg(&fwT4[k * 50 + 32 + lane]);
            acc.x += hv * w.x; acc.y += hv * w.y; acc.z += hv * w.z; acc.w += hv * w.w;
        }
        o4[32 + lane] = acc;
    }
}

extern "C" void kernel_launch(void* const* d_in, const int* in_sizes, int n_in,
                              void* d_out, int out_size) {
    const float* x   = (const float*)d_in[0];
    const float* wb1 = (const float*)d_in[1];
    const float* ws1 = (const float*)d_in[2];
    const float* wb2 = (const float*)d_in[3];
    const float* ws2 = (const float*)d_in[4];
    const float* wb3 = (const float*)d_in[5];
    const float* ws3 = (const float*)d_in[6];
    const float* fcw = (const float*)d_in[7];
    const float* fcb = (const float*)d_in[8];
    float* out = (float*)d_out;

    int B = in_sizes[0] / 784;

    cudaFuncSetAttribute(k2_conv, cudaFuncAttributeMaxDynamicSharedMemorySize, K2_SMEM);
    cudaFuncSetAttribute(k2_conv, cudaFuncAttributePreferredSharedMemoryCarveout, 100);
    cudaFuncSetAttribute(k3_conv, cudaFuncAttributeMaxDynamicSharedMemorySize, K3_SMEM);

    build_tables<<<40, 512>>>(ws2, fcw);
    k1_conv_pool<<<(B + K1_IMGS - 1) / K1_IMGS, 512>>>(x, wb1, ws1, B);
    k2_conv<<<(B + K2_IMGS - 1) / K2_IMGS, 768, K2_SMEM>>>(wb2, B);
    k3_conv<<<(B + K3_IMGS - 1) / K3_IMGS, 512, K3_SMEM>>>(wb3, ws3, B);
    k4_fc<<<(B + K4_WARPS - 1) / K4_WARPS, 512>>>(fcb, out, B);
}

// round 15
// speedup vs baseline: 1.3227x; 1.3227x over previous
#include <cuda_runtime.h>
#include <cuda_fp16.h>
#include <math.h>

// ---------------- global scratch (allocation-free rule) ----------------
static __device__ float2 g_p1[4096 * 845];   // L1 pooled output as {silu, t}
static __device__ float2 g_p2[4096 * 405];   // L2 output as {silu, t}
static __device__ float  g_h[4096 * 98];     // L3 conv output (flattened)
static __device__ float  g_fwT[98 * 200];    // fc_w transposed: [k][o]
static __device__ uint2  g_c2h[625 * 11];    // layer-2 coefs fp16 {c0,c1|c2,c3}, row=o*125+f

__device__ __forceinline__ float silu_f(float x) {
    return __fdividef(x, 1.0f + __expf(-x));
}
__device__ __forceinline__ float tmap(float x) { return (x + 1.0f) * 2.5f + 3.0f; }
__device__ __forceinline__ float cubic4(float4 q, float u) {
    return ((q.w * u + q.z) * u + q.y) * u + q.x;
}
// fp16-packed cubic: unpack to fp32, horner in fp32
__device__ __forceinline__ float cubic_h(uint2 q, float u) {
    float2 c01 = __half22float2(*reinterpret_cast<const __half2*>(&q.x));
    float2 c23 = __half22float2(*reinterpret_cast<const __half2*>(&q.y));
    return ((c23.y * u + c23.x) * u + c01.y) * u + c01.x;
}

__device__ __forceinline__ float4 coef_from_w(const float* __restrict__ ws, int row, int j) {
    float w[4];
#pragma unroll
    for (int k = 0; k < 4; k++) {
        int g = j - 3 + k;
        w[k] = (g >= 0 && g <= 7) ? __ldg(&ws[row * 8 + g]) : 0.0f;
    }
    const float s6 = 1.0f / 6.0f;
    float4 c;
    c.x = (w[0] + 4.0f * w[1] + w[2]) * s6;
    c.y = (w[2] - w[0]) * 0.5f;
    c.z = (w[0] - 2.0f * w[1] + w[2]) * 0.5f;
    c.w = (-w[0] + 3.0f * w[1] - 3.0f * w[2] + w[3]) * s6;
    return c;
}

// ---------------- setup: fp16 layer-2 table + fc_w transpose ----------------
__global__ void build_tables(const float* __restrict__ ws2, const float* __restrict__ fcw) {
    int stride = gridDim.x * blockDim.x;
    int tid = blockIdx.x * blockDim.x + threadIdx.x;
    for (int i = tid; i < 625 * 11; i += stride) {
        float4 q = coef_from_w(ws2, i / 11, i % 11);
        __half2 h01 = __floats2half2_rn(q.x, q.y);
        __half2 h23 = __floats2half2_rn(q.z, q.w);
        uint2 r;
        r.x = *reinterpret_cast<unsigned*>(&h01);
        r.y = *reinterpret_cast<unsigned*>(&h23);
        g_c2h[i] = r;
    }
    for (int i = tid; i < 200 * 98; i += stride) {
        int o = i / 98, k = i % 98;
        g_fwT[k * 200 + o] = fcw[i];
    }
}

// ---------------- Kernel 1: conv3(Cin=1,O=5) + maxpool2, 6 imgs, 512 thr (fp32) ----------------
#define K1_IMGS 6
__global__ void __launch_bounds__(512)
k1_conv_pool(const float* __restrict__ x, const float* __restrict__ wb1,
             const float* __restrict__ ws1, int B) {
    __shared__ __align__(16) float wbTs[9 * 8];
    __shared__ float4 c1s[45 * 11];
    __shared__ float2 px[K1_IMGS * 784];
    int tid = threadIdx.x;
    int b0 = blockIdx.x * K1_IMGS;
    int nimg = min(K1_IMGS, B - b0);

    for (int i = tid; i < 45 * 11; i += 512) c1s[i] = coef_from_w(ws1, i / 11, i % 11);
    if (tid < 72) {
        int f = tid / 8, o = tid % 8;
        wbTs[tid] = (o < 5) ? __ldg(&wb1[o * 9 + f]) : 0.0f;
    }
    for (int i = tid; i < nimg * 784; i += 512) {
        float v = x[b0 * 784 + i];
        px[i] = make_float2(silu_f(v), tmap(v));
    }
    __syncthreads();

    for (int task = tid; task < nimg * 169; task += 512) {
        int li = task / 169, p = task % 169;
        int ph = p / 13, pw = p % 13;

        float s[16], u[16];
        int jj[16];
#pragma unroll
        for (int i = 0; i < 16; i++) {
            int r = i >> 2, c = i & 3;
            float2 st = px[li * 784 + (2 * ph + r) * 28 + 2 * pw + c];
            s[i] = st.x;
            float fj = floorf(st.y);
            jj[i] = (int)fj;
            u[i] = st.y - fj;
        }

        float best[5];
#pragma unroll
        for (int o = 0; o < 5; o++) best[o] = -3.0e38f;

#pragma unroll
        for (int d = 0; d < 4; d++) {
            int dy = d >> 1, dx = d & 1;
            float a0 = 0, a1 = 0, a2 = 0, a3 = 0, a4 = 0;
#pragma unroll
            for (int r = 0; r < 3; r++)
#pragma unroll
            for (int c = 0; c < 3; c++) {
                int f = r * 3 + c;
                int i = (dy + r) * 4 + (dx + c);
                float sv = s[i];
                float4 wbv = *reinterpret_cast<const float4*>(&wbTs[f * 8]);
                float wb4 = wbTs[f * 8 + 4];
                a0 += sv * wbv.x; a1 += sv * wbv.y; a2 += sv * wbv.z;
                a3 += sv * wbv.w; a4 += sv * wb4;
                int j = jj[i];
                float uu = u[i];
                if ((unsigned)j <= 10u) {
                    int i0 = f * 11 + j;
                    a0 += cubic4(c1s[i0], uu);
                    a1 += cubic4(c1s[i0 + 99], uu);
                    a2 += cubic4(c1s[i0 + 198], uu);
                    a3 += cubic4(c1s[i0 + 297], uu);
                    a4 += cubic4(c1s[i0 + 396], uu);
                }
            }
            best[0] = fmaxf(best[0], a0); best[1] = fmaxf(best[1], a1);
            best[2] = fmaxf(best[2], a2); best[3] = fmaxf(best[3], a3);
            best[4] = fmaxf(best[4], a4);
        }
#pragma unroll
        for (int o = 0; o < 5; o++) {
            float v = best[o];
            g_p1[(b0 + li) * 845 + o * 169 + p] = make_float2(silu_f(v), tmap(v));
        }
    }
}

// ---------------- Kernel 2: conv5(Cin=5,O=5), fp16 coefs, 6 imgs, 512 thr, 2 blk/SM ----------------
// smem (bytes): wbTs [0,4000) 16-aligned; c2h uint2 [4000,59000); in float2 [59000,99560)
#define K2_IMGS 6
#define K2_SMEM (4000 + 55000 + K2_IMGS * 845 * 8)
__global__ void __launch_bounds__(512, 2)
k2_conv(const float* __restrict__ wb2, int B) {
    extern __shared__ __align__(16) char smraw[];
    float* wbTs = reinterpret_cast<float*>(smraw);             // 1000
    uint2* c2h  = reinterpret_cast<uint2*>(smraw + 4000);      // 6875
    float2* in  = reinterpret_cast<float2*>(smraw + 59000);    // 6*845
    int tid = threadIdx.x;
    int b0 = blockIdx.x * K2_IMGS;
    int nimg = min(K2_IMGS, B - b0);

    for (int i = tid; i < 6875; i += 512) c2h[i] = g_c2h[i];   // coalesced copy
    for (int i = tid; i < 1000; i += 512) {
        int f = i / 8, o = i % 8;
        wbTs[i] = (o < 5) ? __ldg(&wb2[o * 125 + f]) : 0.0f;
    }
    for (int i = tid; i < nimg * 845; i += 512) in[i] = g_p1[b0 * 845 + i];
    __syncthreads();

    int li = tid / 81, pos = tid % 81;
    if (li >= nimg) return;
    int oy = pos / 9, ox = pos % 9;

    float a0 = 0, a1 = 0, a2 = 0, a3 = 0, a4 = 0;
    for (int c = 0; c < 5; c++) {
        const float2* inc = &in[li * 845 + c * 169];
        for (int kh = 0; kh < 5; kh++) {
            const float2* row = &inc[(oy + kh) * 13 + ox];
            int fbase = (c * 5 + kh) * 5;
#pragma unroll
            for (int kw = 0; kw < 5; kw++) {
                int f = fbase + kw;
                float2 st = row[kw];
                float4 wbv = *reinterpret_cast<const float4*>(&wbTs[f * 8]);
                float wb4 = wbTs[f * 8 + 4];
                a0 += st.x * wbv.x; a1 += st.x * wbv.y; a2 += st.x * wbv.z;
                a3 += st.x * wbv.w; a4 += st.x * wb4;
                float fj = floorf(st.y);
                int j = (int)fj;
                float u = st.y - fj;
                if ((unsigned)j <= 10u) {
                    int i0 = f * 11 + j;
                    a0 += cubic_h(c2h[i0], u);
                    a1 += cubic_h(c2h[i0 + 1375], u);
                    a2 += cubic_h(c2h[i0 + 2750], u);
                    a3 += cubic_h(c2h[i0 + 4125], u);
                    a4 += cubic_h(c2h[i0 + 5500], u);
                }
            }
        }
    }
    int b = b0 + li;
    float acc[5] = {a0, a1, a2, a3, a4};
#pragma unroll
    for (int o = 0; o < 5; o++) {
        float v = acc[o];
        g_p2[b * 405 + o * 81 + pos] = make_float2(silu_f(v), tmap(v));
    }
}

// ---------------- Kernel 3: conv3(Cin=5,O=2), 10 imgs, 512 thr -> g_h (fp32) ----------------
#define K3_IMGS 10
#define K3_SMEM (15840 + K3_IMGS * 405 * 8 + 45 * 8)
__global__ void __launch_bounds__(512)
k3_conv(const float* __restrict__ wb3, const float* __restrict__ ws3, int B) {
    extern __shared__ __align__(16) char smraw3[];
    float4* c3s = reinterpret_cast<float4*>(smraw3);             // 990
    float2* in  = reinterpret_cast<float2*>(smraw3 + 15840);     // 10*405
    float2* wbp = reinterpret_cast<float2*>(smraw3 + 15840 + K3_IMGS * 405 * 8); // 45
    int tid = threadIdx.x;
    int b0 = blockIdx.x * K3_IMGS;
    int nimg = min(K3_IMGS, B - b0);

    for (int i = tid; i < 990; i += 512) c3s[i] = coef_from_w(ws3, i / 11, i % 11);
    if (tid < 45) wbp[tid] = make_float2(__ldg(&wb3[tid]), __ldg(&wb3[45 + tid]));
    for (int i = tid; i < nimg * 405; i += 512) in[i] = g_p2[b0 * 405 + i];
    __syncthreads();

    for (int task = tid; task < nimg * 49; task += 512) {
        int li = task / 49, pos = task % 49;
        int oy = pos / 7, ox = pos % 7;
        float a0 = 0, a1 = 0;
        for (int c = 0; c < 5; c++) {
#pragma unroll
            for (int kh = 0; kh < 3; kh++)
#pragma unroll
            for (int kw = 0; kw < 3; kw++) {
                int f = (c * 3 + kh) * 3 + kw;
                float2 st = in[li * 405 + c * 81 + (oy + kh) * 9 + ox + kw];
                float2 wv = wbp[f];
                a0 += st.x * wv.x;
                a1 += st.x * wv.y;
                float fj = floorf(st.y);
                int j = (int)fj;
                float u = st.y - fj;
                if ((unsigned)j <= 10u) {
                    int i0 = f * 11 + j;
                    a0 += cubic4(c3s[i0], u);
                    a1 += cubic4(c3s[i0 + 495], u);
                }
            }
        }
        int b = b0 + li;
        g_h[b * 98 + pos]      = a0;   // flatten order o*49 + pos
        g_h[b * 98 + 49 + pos] = a1;
    }
}

// ---------------- Kernel 4: FC, warp-per-image, fwT via LDG (L1-resident) ----------------
#define K4_WARPS 16
__global__ void __launch_bounds__(512)
k4_fc(const float* __restrict__ fcb, float* __restrict__ out, int B) {
    __shared__ float hs[K4_WARPS][100];
    int tid = threadIdx.x;
    int wid = tid / 32, lane = tid % 32;
    int img = blockIdx.x * K4_WARPS + wid;
    if (img >= B) return;

    for (int k = lane; k < 98; k += 32) hs[wid][k] = g_h[img * 98 + k];
    __syncwarp();

    const float4* fwT4 = reinterpret_cast<const float4*>(g_fwT);
    const float4* fb4  = reinterpret_cast<const float4*>(fcb);
    const float*  hr   = hs[wid];
    float4* o4 = reinterpret_cast<float4*>(out + img * 200);

    {
        float4 acc = __ldg(&fb4[lane]);
#pragma unroll 7
        for (int k = 0; k < 98; k++) {
            float hv = hr[k];
            float4 w = __ldg(&fwT4[k * 50 + lane]);
            acc.x += hv * w.x; acc.y += hv * w.y; acc.z += hv * w.z; acc.w += hv * w.w;
        }
        o4[lane] = acc;
    }
    if (lane < 18) {
        float4 acc = __ldg(&fb4[32 + lane]);
#pragma unroll 7
        for (int k = 0; k < 98; k++) {
            float hv = hr[k];
            float4 w = __ldg(&fwT4[k * 50 + 32 + lane]);
            acc.x += hv * w.x; acc.y += hv * w.y; acc.z += hv * w.z; acc.w += hv * w.w;
        }
        o4[32 + lane] = acc;
    }
}

extern "C" void kernel_launch(void* const* d_in, const int* in_sizes, int n_in,
                              void* d_out, int out_size) {
    const float* x   = (const float*)d_in[0];
    const float* wb1 = (const float*)d_in[1];
    const float* ws1 = (const float*)d_in[2];
    const float* wb2 = (const float*)d_in[3];
    const float* ws2 = (const float*)d_in[4];
    const float* wb3 = (const float*)d_in[5];
    const float* ws3 = (const float*)d_in[6];
    const float* fcw = (const float*)d_in[7];
    const float* fcb = (const float*)d_in[8];
    float* out = (float*)d_out;

    int B = in_sizes[0] / 784;

    cudaFuncSetAttribute(k2_conv, cudaFuncAttributeMaxDynamicSharedMemorySize, K2_SMEM);
    cudaFuncSetAttribute(k2_conv, cudaFuncAttributePreferredSharedMemoryCarveout, 100);
    cudaFuncSetAttribute(k3_conv, cudaFuncAttributeMaxDynamicSharedMemorySize, K3_SMEM);

    build_tables<<<40, 512>>>(ws2, fcw);
    k1_conv_pool<<<(B + K1_IMGS - 1) / K1_IMGS, 512>>>(x, wb1, ws1, B);
    k2_conv<<<(B + K2_IMGS - 1) / K2_IMGS, 512, K2_SMEM>>>(wb2, B);
    k3_conv<<<(B + K3_IMGS - 1) / K3_IMGS, 512, K3_SMEM>>>(wb3, ws3, B);
    k4_fc<<<(B + K4_WARPS - 1) / K4_WARPS, 512>>>(fcb, out, B);
}